// round 14
// baseline (speedup 1.0000x reference)
#include <cuda_runtime.h>
#include <cuda_bf16.h>
#include <cstdint>

// ============================================================================
// out[n,o] = act_scale*wscale[o] * sum_k qa[n,k]*qw[o,k] + bias[o]
//   qa = clamp(rint(x/as), -128, 127)  (zp=128 cancels in (q-zp))
// Portable tensor-core path: cp.async + ldmatrix + mma.sync.m16n8k32.s8.
// R14: B operand bypasses SMEM entirely. Quant pre-packs B into mma-fragment-
//      linear 512B blocks; GEMM loads B fragments with one coalesced LDG.128
//      per (nj,ks), register double-buffered one ks ahead (constant indices).
//      A stays on the proven cp.async/ldmatrix path (stage now 16 KB only).
//      Keeps 4-phase address-only ks stagger + direct-global epilogue.
// ============================================================================

#define NROWS 4096
#define KDIM  4096
#define ODIM  4096

#define BM 128
#define BN 128
#define BK 128
#define STAGES 3
#define KTILES (KDIM / BK)                        // 32
#define STAGE_BYTES (BM * BK)                     // 16384 (A only)
#define GEMM_SMEM (STAGES * STAGE_BYTES + 1024)   // 50176

__device__ __align__(128) int8_t g_Aq[(size_t)NROWS * KDIM];  // 16 MB row-major
__device__ __align__(128) int8_t g_Bq[(size_t)ODIM * KDIM];   // 16 MB frag-packed

// ---------------------------------------------------------------------------
__device__ __forceinline__ uint32_t smem_u32(const void* p) {
    uint32_t a;
    asm("{ .reg .u64 t; cvta.to.shared.u64 t, %1; cvt.u32.u64 %0, t; }"
        : "=r"(a) : "l"(p));
    return a;
}
__device__ __forceinline__ void cp_async16(uint32_t dst, const void* src) {
    asm volatile("cp.async.cg.shared.global [%0], [%1], 16;"
                 :: "r"(dst), "l"(src) : "memory");
}
__device__ __forceinline__ void cp_commit() {
    asm volatile("cp.async.commit_group;" ::: "memory");
}
template <int N>
__device__ __forceinline__ void cp_wait() {
    asm volatile("cp.async.wait_group %0;" :: "n"(N) : "memory");
}
__device__ __forceinline__ void ldmatrix_x4(uint32_t* r, uint32_t addr) {
    asm volatile("ldmatrix.sync.aligned.m8n8.x4.shared.b16 {%0,%1,%2,%3}, [%4];"
                 : "=r"(r[0]), "=r"(r[1]), "=r"(r[2]), "=r"(r[3]) : "r"(addr));
}
__device__ __forceinline__ void mma_s8(int* c, const uint32_t* a, const uint32_t* b) {
    asm volatile(
        "mma.sync.aligned.m16n8k32.row.col.s32.s8.s8.s32 "
        "{%0,%1,%2,%3}, {%4,%5,%6,%7}, {%8,%9}, {%0,%1,%2,%3};"
        : "+r"(c[0]), "+r"(c[1]), "+r"(c[2]), "+r"(c[3])
        : "r"(a[0]), "r"(a[1]), "r"(a[2]), "r"(a[3]), "r"(b[0]), "r"(b[1]));
}

// ---------------------------------------------------------------------------
// Fused quantize.
// Blocks [0, QB): activations -> g_Aq row-major, 16 elems/thread.
// Blocks [QB, QB+QB2): weights -> g_Bq fragment-packed, 32 elems/thread.
//   Fragment block (n16 = n/16, k32 = k/32) = 512 B at ((n16*128 + k32) << 9).
//   Lane slot L (0..31) = 16 B: [0:4)=B[n16*16+L/4][k32*32+(L%4)*4..+3],
//   [4:8) same rows k+16, [8:12)=rows +8 k-lo, [12:16) rows +8 k-hi.
// ---------------------------------------------------------------------------
#define QB  4096
#define QB2 2048

__device__ __forceinline__ uint32_t quant_pack4(const float* v, float inv, float zp) {
    uint32_t w = 0;
#pragma unroll
    for (int i = 0; i < 4; ++i) {
        float t = rintf(v[i] * inv) + zp;
        t = fminf(fmaxf(t, 0.0f), 255.0f);
        int q = (int)t - (int)zp;
        w |= ((uint32_t)q & 0xFFu) << (i * 8);
    }
    return w;
}

__global__ void __launch_bounds__(256)
quant_fused_kernel(const float* __restrict__ x, const float* __restrict__ asp,
                   const int* __restrict__ azp,
                   const float* __restrict__ w, const float* __restrict__ wsc,
                   const int* __restrict__ wzp)
{
    if (blockIdx.x < QB) {
        // ---- activations: row-major int8 ----
        size_t base = ((size_t)blockIdx.x * 256 + threadIdx.x) * 16;
        float inv = 1.0f / *asp;
        float zp = (float)(*azp);
        float v[16];
        *reinterpret_cast<float4*>(v)      = *reinterpret_cast<const float4*>(x + base);
        *reinterpret_cast<float4*>(v + 4)  = *reinterpret_cast<const float4*>(x + base + 4);
        *reinterpret_cast<float4*>(v + 8)  = *reinterpret_cast<const float4*>(x + base + 8);
        *reinterpret_cast<float4*>(v + 12) = *reinterpret_cast<const float4*>(x + base + 12);
        uint4 o;
        o.x = quant_pack4(v,      inv, zp);
        o.y = quant_pack4(v + 4,  inv, zp);
        o.z = quant_pack4(v + 8,  inv, zp);
        o.w = quant_pack4(v + 12, inv, zp);
        *reinterpret_cast<uint4*>(g_Aq + base) = o;
    } else {
        // ---- weights: fragment-packed ----
        int t = (blockIdx.x - QB) * 256 + threadIdx.x;   // 0..524287
        int n   = t >> 7;                                // row 0..4095
        int k32 = t & 127;                               // 32-k chunk
        float inv = 1.0f / wsc[n];
        float zp  = (float)wzp[n];
        const float* src = w + (size_t)n * KDIM + k32 * 32;
        float v[32];
#pragma unroll
        for (int j = 0; j < 8; ++j)
            *reinterpret_cast<float4*>(v + j * 4) =
                *reinterpret_cast<const float4*>(src + j * 4);
        uint32_t q[8];
#pragma unroll
        for (int j = 0; j < 8; ++j) q[j] = quant_pack4(v + j * 4, inv, zp);
        // q[w] covers k = k32*32 + 4w .. +3 ; q[4+w] covers +16
        int8_t* blk = g_Bq + (((size_t)((n >> 4) * 128 + k32)) << 9);
        int L0 = (n & 7) * 4;
        int o_n = (n & 8) ? 8 : 0;
#pragma unroll
        for (int ww = 0; ww < 4; ++ww) {
            uint2 val;
            val.x = q[ww];
            val.y = q[4 + ww];
            *reinterpret_cast<uint2*>(blk + (L0 + ww) * 16 + o_n) = val;
        }
    }
}

// ---------------------------------------------------------------------------
// GEMM: 128x128 per CTA, 8 warps (4x2), warp tile 32x64, IMMA m16n8k32.s8,
// 2 CTAs/SM. A via cp.async+ldmatrix (16 KB stages, XOR swizzle). B via
// direct LDG.128 of fragment-packed blocks, double-buffered one ks ahead.
// ---------------------------------------------------------------------------
__device__ __forceinline__ void load_stage(uint32_t stA, int m0, int kt, int tid)
{
#pragma unroll
    for (int i = 0; i < 4; ++i) {
        int id = tid + i * 256;           // A: 128 rows x 8 chunks
        int row = id >> 3, ch = id & 7;
        cp_async16(stA + row * BK + (((uint32_t)(ch ^ (row & 7))) << 4),
                   g_Aq + (size_t)(m0 + row) * KDIM + kt * BK + ch * 16);
    }
}

__device__ __forceinline__ void ldB(uint32_t* B, int n16base, int k32, int lane)
{
    const int8_t* p = g_Bq + (((size_t)(n16base * 128 + k32)) << 9) + lane * 16;
#pragma unroll
    for (int nj = 0; nj < 4; ++nj) {      // nj: n16base+nj -> +nj*128*512 bytes
        uint4 v = *reinterpret_cast<const uint4*>(p + (size_t)nj * 65536);
        B[nj * 4 + 0] = v.x;  B[nj * 4 + 1] = v.y;
        B[nj * 4 + 2] = v.z;  B[nj * 4 + 3] = v.w;
    }
}

__device__ __forceinline__ void mma_block(int (*acc)[8][4], const uint32_t (*aF)[4],
                                          const uint32_t* B)
{
#pragma unroll
    for (int nj = 0; nj < 4; ++nj) {
        uint32_t b0[2] = { B[nj * 4 + 0], B[nj * 4 + 1] };   // rows n+0..7
        uint32_t b1[2] = { B[nj * 4 + 2], B[nj * 4 + 3] };   // rows n+8..15
        mma_s8(acc[0][nj * 2],     aF[0], b0);
        mma_s8(acc[0][nj * 2 + 1], aF[0], b1);
        mma_s8(acc[1][nj * 2],     aF[1], b0);
        mma_s8(acc[1][nj * 2 + 1], aF[1], b1);
    }
}

__device__ __forceinline__ void ldA(uint32_t (*aF)[4], uint32_t aT, int ks,
                                    int wm, int rsel, int csel)
{
    const int ch = ks * 2 + csel;
#pragma unroll
    for (int mi = 0; mi < 2; ++mi) {
        int row = wm * 32 + mi * 16 + rsel;
        ldmatrix_x4(aF[mi], aT + row * BK + (((uint32_t)(ch ^ (row & 7))) << 4));
    }
}

__global__ void __launch_bounds__(256, 2)
gemm_q_kernel(const float* __restrict__ bias, const float* __restrict__ act_scale_p,
              const float* __restrict__ wscale, float* __restrict__ out)
{
    extern __shared__ char smem[];
    const uint32_t sb = (smem_u32(smem) + 1023u) & ~1023u;
    const int tid = threadIdx.x;
    const int lane = tid & 31;
    const int wid = tid >> 5;
    const int wm = wid & 3;               // 0..3 (32-row slices)
    const int wn = wid >> 2;              // 0..1 (64-col slices)
    const int phase = ((((wid >> 2) << 1) | (wid & 1))
                       + (int)((blockIdx.x + blockIdx.y) & 3)) & 3;
    const int m0 = blockIdx.y * BM;
    const int n0 = blockIdx.x * BN;
    const int n16base = (n0 >> 4) + wn * 4;

    int acc[2][8][4];
#pragma unroll
    for (int mi = 0; mi < 2; ++mi)
#pragma unroll
        for (int ni = 0; ni < 8; ++ni)
#pragma unroll
            for (int j = 0; j < 4; ++j) acc[mi][ni][j] = 0;

#pragma unroll
    for (int s = 0; s < STAGES - 1; ++s) {
        load_stage(sb + s * STAGE_BYTES, m0, s, tid);
        cp_commit();
    }

    const int mat = lane >> 3;
    const int rsel = (lane & 7) + (mat & 1) * 8;
    const int csel = mat >> 1;

    uint32_t B0[16], B1[16];
    ldB(B0, n16base, 0 * 4 + (phase & 3), lane);      // prologue: kt=0, ksi=0

    for (int kt = 0; kt < KTILES; ++kt) {
        cp_wait<STAGES - 2>();
        __syncthreads();

        int nxt = kt + STAGES - 1;
        if (nxt < KTILES)
            load_stage(sb + (nxt % STAGES) * STAGE_BYTES, m0, nxt, tid);
        cp_commit();

        const uint32_t aT = sb + (kt % STAGES) * STAGE_BYTES;
        uint32_t aF[2][4];

        // ksi = 0: use B0, prefetch B1 (ksi=1)
        ldB(B1, n16base, kt * 4 + ((1 + phase) & 3), lane);
        ldA(aF, aT, (0 + phase) & 3, wm, rsel, csel);
        mma_block(acc, aF, B0);
        // ksi = 1: use B1, prefetch B0 (ksi=2)
        ldB(B0, n16base, kt * 4 + ((2 + phase) & 3), lane);
        ldA(aF, aT, (1 + phase) & 3, wm, rsel, csel);
        mma_block(acc, aF, B1);
        // ksi = 2: use B0, prefetch B1 (ksi=3)
        ldB(B1, n16base, kt * 4 + ((3 + phase) & 3), lane);
        ldA(aF, aT, (2 + phase) & 3, wm, rsel, csel);
        mma_block(acc, aF, B0);
        // ksi = 3: use B1, prefetch B0 (kt+1, ksi=0)
        if (kt + 1 < KTILES)
            ldB(B0, n16base, (kt + 1) * 4 + (phase & 3), lane);
        ldA(aF, aT, (3 + phase) & 3, wm, rsel, csel);
        mma_block(acc, aF, B1);
    }
    cp_wait<0>();

    // ---- epilogue: scale + bias, direct-to-global (no staging, no syncs) ----
    const float as = *act_scale_p;
    const int r4 = lane >> 2;             // 0..7
    const int c2 = (lane & 3) * 2;        // 0,2,4,6

#pragma unroll
    for (int ni = 0; ni < 8; ++ni) {
        int gc = n0 + wn * 64 + ni * 8 + c2;
        float sw0 = as * wscale[gc],     bv0 = bias[gc];
        float sw1 = as * wscale[gc + 1], bv1 = bias[gc + 1];
#pragma unroll
        for (int mi = 0; mi < 2; ++mi) {
            int r = m0 + wm * 32 + mi * 16 + r4;
            float2 v0, v1;
            v0.x = fmaf(__int2float_rn(acc[mi][ni][0]), sw0, bv0);
            v0.y = fmaf(__int2float_rn(acc[mi][ni][1]), sw1, bv1);
            v1.x = fmaf(__int2float_rn(acc[mi][ni][2]), sw0, bv0);
            v1.y = fmaf(__int2float_rn(acc[mi][ni][3]), sw1, bv1);
            *reinterpret_cast<float2*>(&out[(size_t)r * ODIM + gc])       = v0;
            *reinterpret_cast<float2*>(&out[(size_t)(r + 8) * ODIM + gc]) = v1;
        }
    }
}

// ---------------------------------------------------------------------------
extern "C" void kernel_launch(void* const* d_in, const int* in_sizes, int n_in,
                              void* d_out, int out_size) {
    (void)in_sizes; (void)n_in; (void)out_size;
    const float* x         = (const float*)d_in[0];
    const float* weight    = (const float*)d_in[1];
    const float* bias      = (const float*)d_in[2];
    const float* act_scale = (const float*)d_in[3];
    const int*   act_zp    = (const int*)d_in[4];
    const float* wscale    = (const float*)d_in[5];
    const int*   wzp       = (const int*)d_in[6];
    float* out = (float*)d_out;

    cudaFuncSetAttribute(gemm_q_kernel, cudaFuncAttributeMaxDynamicSharedMemorySize, GEMM_SMEM);

    quant_fused_kernel<<<QB + QB2, 256>>>(x, act_scale, act_zp, weight, wscale, wzp);

    dim3 grid(ODIM / BN, NROWS / BM);   // (32, 32)
    gemm_q_kernel<<<grid, 256, GEMM_SMEM>>>(bias, act_scale, wscale, out);
}

// round 15
// speedup vs baseline: 1.0876x; 1.0876x over previous
#include <cuda_runtime.h>
#include <cuda_bf16.h>
#include <cstdint>

// ============================================================================
// out[n,o] = act_scale*wscale[o] * sum_k qa[n,k]*qw[o,k] + bias[o]
//   qa = clamp(rint(x/as), -128, 127)  (zp=128 cancels in (q-zp))
// Portable tensor-core path: cp.async + ldmatrix + mma.sync.m16n8k32.s8.
// R15: R14 GEMM (B via fragment-packed LDG.128, reg double-buffered; A via
//      cp.async SMEM pipeline) with STAGES=4, plus warp-per-block COALESCED
//      fragment-packing weight quant (R14's B-quant stores were 512B-strided
//      8B scribbles; now one uint4 per lane = 512B/warp coalesced).
// ============================================================================

#define NROWS 4096
#define KDIM  4096
#define ODIM  4096

#define BM 128
#define BN 128
#define BK 128
#define STAGES 4
#define KTILES (KDIM / BK)                        // 32
#define STAGE_BYTES (BM * BK)                     // 16384 (A only)
#define GEMM_SMEM (STAGES * STAGE_BYTES + 1024)   // 66560 -> 2 CTAs/SM

__device__ __align__(128) int8_t g_Aq[(size_t)NROWS * KDIM];  // 16 MB row-major
__device__ __align__(128) int8_t g_Bq[(size_t)ODIM * KDIM];   // 16 MB frag-packed

// ---------------------------------------------------------------------------
__device__ __forceinline__ uint32_t smem_u32(const void* p) {
    uint32_t a;
    asm("{ .reg .u64 t; cvta.to.shared.u64 t, %1; cvt.u32.u64 %0, t; }"
        : "=r"(a) : "l"(p));
    return a;
}
__device__ __forceinline__ void cp_async16(uint32_t dst, const void* src) {
    asm volatile("cp.async.cg.shared.global [%0], [%1], 16;"
                 :: "r"(dst), "l"(src) : "memory");
}
__device__ __forceinline__ void cp_commit() {
    asm volatile("cp.async.commit_group;" ::: "memory");
}
template <int N>
__device__ __forceinline__ void cp_wait() {
    asm volatile("cp.async.wait_group %0;" :: "n"(N) : "memory");
}
__device__ __forceinline__ void ldmatrix_x4(uint32_t* r, uint32_t addr) {
    asm volatile("ldmatrix.sync.aligned.m8n8.x4.shared.b16 {%0,%1,%2,%3}, [%4];"
                 : "=r"(r[0]), "=r"(r[1]), "=r"(r[2]), "=r"(r[3]) : "r"(addr));
}
__device__ __forceinline__ void mma_s8(int* c, const uint32_t* a, const uint32_t* b) {
    asm volatile(
        "mma.sync.aligned.m16n8k32.row.col.s32.s8.s8.s32 "
        "{%0,%1,%2,%3}, {%4,%5,%6,%7}, {%8,%9}, {%0,%1,%2,%3};"
        : "+r"(c[0]), "+r"(c[1]), "+r"(c[2]), "+r"(c[3])
        : "r"(a[0]), "r"(a[1]), "r"(a[2]), "r"(a[3]), "r"(b[0]), "r"(b[1]));
}

// ---------------------------------------------------------------------------
// Fused quantize.
// Blocks [0, QB): activations -> g_Aq row-major, 16 elems/thread (coalesced).
// Blocks [QB, QB+QB2): weights -> g_Bq fragment-packed, WARP-PER-BLOCK:
//   512B block (n16, k32) at ((n16*128 + k32) << 9); lane L writes slot L
//   (16 B, one uint4): [0:4)=B[n16*16+L/4][k32*32+(L%4)*4..+3], [4:8) +16 k,
//   [8:12)=row +8 k-lo, [12:16)=row +8 k-hi.  (Byte-identical to R14 layout.)
// ---------------------------------------------------------------------------
#define QB  4096
#define QB2 4096   // 32768 blocks / 8 warps per 256-thread CTA

__device__ __forceinline__ uint32_t quant_pack4(const float* v, float inv, float zp) {
    uint32_t w = 0;
#pragma unroll
    for (int i = 0; i < 4; ++i) {
        float t = rintf(v[i] * inv) + zp;
        t = fminf(fmaxf(t, 0.0f), 255.0f);
        int q = (int)t - (int)zp;
        w |= ((uint32_t)q & 0xFFu) << (i * 8);
    }
    return w;
}

__global__ void __launch_bounds__(256)
quant_fused_kernel(const float* __restrict__ x, const float* __restrict__ asp,
                   const int* __restrict__ azp,
                   const float* __restrict__ w, const float* __restrict__ wsc,
                   const int* __restrict__ wzp)
{
    if (blockIdx.x < QB) {
        // ---- activations: row-major int8, fully coalesced ----
        size_t base = ((size_t)blockIdx.x * 256 + threadIdx.x) * 16;
        float inv = 1.0f / *asp;
        float zp = (float)(*azp);
        float v[16];
        *reinterpret_cast<float4*>(v)      = *reinterpret_cast<const float4*>(x + base);
        *reinterpret_cast<float4*>(v + 4)  = *reinterpret_cast<const float4*>(x + base + 4);
        *reinterpret_cast<float4*>(v + 8)  = *reinterpret_cast<const float4*>(x + base + 8);
        *reinterpret_cast<float4*>(v + 12) = *reinterpret_cast<const float4*>(x + base + 12);
        uint4 o;
        o.x = quant_pack4(v,      inv, zp);
        o.y = quant_pack4(v + 4,  inv, zp);
        o.z = quant_pack4(v + 8,  inv, zp);
        o.w = quant_pack4(v + 12, inv, zp);
        *reinterpret_cast<uint4*>(g_Aq + base) = o;
    } else {
        // ---- weights: warp-per-block fragment packing ----
        int wlin = (blockIdx.x - QB) * 8 + ((int)threadIdx.x >> 5); // 0..32767
        int lane = threadIdx.x & 31;
        int n16 = wlin >> 7;                       // 0..255
        int k32 = wlin & 127;                      // 0..127
        int r0 = n16 * 16 + (lane >> 2);           // rows r0 and r0+8
        int k  = k32 * 32 + (lane & 3) * 4;
        const float* p0 = w + (size_t)r0 * KDIM + k;
        const float* p1 = p0 + (size_t)8 * KDIM;
        float4 a0 = *reinterpret_cast<const float4*>(p0);
        float4 a1 = *reinterpret_cast<const float4*>(p0 + 16);
        float4 a2 = *reinterpret_cast<const float4*>(p1);
        float4 a3 = *reinterpret_cast<const float4*>(p1 + 16);
        float inv0 = 1.0f / wsc[r0],     zp0 = (float)wzp[r0];
        float inv1 = 1.0f / wsc[r0 + 8], zp1 = (float)wzp[r0 + 8];
        uint4 o;
        o.x = quant_pack4(reinterpret_cast<const float*>(&a0), inv0, zp0);
        o.y = quant_pack4(reinterpret_cast<const float*>(&a1), inv0, zp0);
        o.z = quant_pack4(reinterpret_cast<const float*>(&a2), inv1, zp1);
        o.w = quant_pack4(reinterpret_cast<const float*>(&a3), inv1, zp1);
        *reinterpret_cast<uint4*>(g_Bq + (((size_t)wlin) << 9) + lane * 16) = o;
    }
}

// ---------------------------------------------------------------------------
// GEMM: 128x128 per CTA, 8 warps (4x2), warp tile 32x64, IMMA m16n8k32.s8,
// 2 CTAs/SM. A via cp.async+ldmatrix (16 KB stages, XOR swizzle). B via
// direct LDG.128 of fragment-packed blocks, double-buffered one ks ahead.
// 4-phase address-only ks stagger; direct-global epilogue.
// ---------------------------------------------------------------------------
__device__ __forceinline__ void load_stage(uint32_t stA, int m0, int kt, int tid)
{
#pragma unroll
    for (int i = 0; i < 4; ++i) {
        int id = tid + i * 256;           // A: 128 rows x 8 chunks
        int row = id >> 3, ch = id & 7;
        cp_async16(stA + row * BK + (((uint32_t)(ch ^ (row & 7))) << 4),
                   g_Aq + (size_t)(m0 + row) * KDIM + kt * BK + ch * 16);
    }
}

__device__ __forceinline__ void ldB(uint32_t* B, int n16base, int k32, int lane)
{
    const int8_t* p = g_Bq + (((size_t)(n16base * 128 + k32)) << 9) + lane * 16;
#pragma unroll
    for (int nj = 0; nj < 4; ++nj) {      // nj: n16base+nj -> +nj*128*512 bytes
        uint4 v = *reinterpret_cast<const uint4*>(p + (size_t)nj * 65536);
        B[nj * 4 + 0] = v.x;  B[nj * 4 + 1] = v.y;
        B[nj * 4 + 2] = v.z;  B[nj * 4 + 3] = v.w;
    }
}

__device__ __forceinline__ void mma_block(int (*acc)[8][4], const uint32_t (*aF)[4],
                                          const uint32_t* B)
{
#pragma unroll
    for (int nj = 0; nj < 4; ++nj) {
        uint32_t b0[2] = { B[nj * 4 + 0], B[nj * 4 + 1] };   // rows n+0..7
        uint32_t b1[2] = { B[nj * 4 + 2], B[nj * 4 + 3] };   // rows n+8..15
        mma_s8(acc[0][nj * 2],     aF[0], b0);
        mma_s8(acc[0][nj * 2 + 1], aF[0], b1);
        mma_s8(acc[1][nj * 2],     aF[1], b0);
        mma_s8(acc[1][nj * 2 + 1], aF[1], b1);
    }
}

__device__ __forceinline__ void ldA(uint32_t (*aF)[4], uint32_t aT, int ks,
                                    int wm, int rsel, int csel)
{
    const int ch = ks * 2 + csel;
#pragma unroll
    for (int mi = 0; mi < 2; ++mi) {
        int row = wm * 32 + mi * 16 + rsel;
        ldmatrix_x4(aF[mi], aT + row * BK + (((uint32_t)(ch ^ (row & 7))) << 4));
    }
}

__global__ void __launch_bounds__(256, 2)
gemm_q_kernel(const float* __restrict__ bias, const float* __restrict__ act_scale_p,
              const float* __restrict__ wscale, float* __restrict__ out)
{
    extern __shared__ char smem[];
    const uint32_t sb = (smem_u32(smem) + 1023u) & ~1023u;
    const int tid = threadIdx.x;
    const int lane = tid & 31;
    const int wid = tid >> 5;
    const int wm = wid & 3;               // 0..3 (32-row slices)
    const int wn = wid >> 2;              // 0..1 (64-col slices)
    const int phase = ((((wid >> 2) << 1) | (wid & 1))
                       + (int)((blockIdx.x + blockIdx.y) & 3)) & 3;
    const int m0 = blockIdx.y * BM;
    const int n0 = blockIdx.x * BN;
    const int n16base = (n0 >> 4) + wn * 4;

    int acc[2][8][4];
#pragma unroll
    for (int mi = 0; mi < 2; ++mi)
#pragma unroll
        for (int ni = 0; ni < 8; ++ni)
#pragma unroll
            for (int j = 0; j < 4; ++j) acc[mi][ni][j] = 0;

#pragma unroll
    for (int s = 0; s < STAGES - 1; ++s) {
        load_stage(sb + s * STAGE_BYTES, m0, s, tid);
        cp_commit();
    }

    const int mat = lane >> 3;
    const int rsel = (lane & 7) + (mat & 1) * 8;
    const int csel = mat >> 1;

    uint32_t B0[16], B1[16];
    ldB(B0, n16base, 0 * 4 + (phase & 3), lane);      // prologue: kt=0, ksi=0

    for (int kt = 0; kt < KTILES; ++kt) {
        cp_wait<STAGES - 2>();
        __syncthreads();

        int nxt = kt + STAGES - 1;
        if (nxt < KTILES)
            load_stage(sb + (nxt % STAGES) * STAGE_BYTES, m0, nxt, tid);
        cp_commit();

        const uint32_t aT = sb + (kt % STAGES) * STAGE_BYTES;
        uint32_t aF[2][4];

        // ksi = 0: use B0, prefetch B1 (ksi=1)
        ldB(B1, n16base, kt * 4 + ((1 + phase) & 3), lane);
        ldA(aF, aT, (0 + phase) & 3, wm, rsel, csel);
        mma_block(acc, aF, B0);
        // ksi = 1: use B1, prefetch B0 (ksi=2)
        ldB(B0, n16base, kt * 4 + ((2 + phase) & 3), lane);
        ldA(aF, aT, (1 + phase) & 3, wm, rsel, csel);
        mma_block(acc, aF, B1);
        // ksi = 2: use B0, prefetch B1 (ksi=3)
        ldB(B1, n16base, kt * 4 + ((3 + phase) & 3), lane);
        ldA(aF, aT, (2 + phase) & 3, wm, rsel, csel);
        mma_block(acc, aF, B0);
        // ksi = 3: use B1, prefetch B0 (kt+1, ksi=0)
        if (kt + 1 < KTILES)
            ldB(B0, n16base, (kt + 1) * 4 + (phase & 3), lane);
        ldA(aF, aT, (3 + phase) & 3, wm, rsel, csel);
        mma_block(acc, aF, B1);
    }
    cp_wait<0>();

    // ---- epilogue: scale + bias, direct-to-global (no staging, no syncs) ----
    const float as = *act_scale_p;
    const int r4 = lane >> 2;             // 0..7
    const int c2 = (lane & 3) * 2;        // 0,2,4,6

#pragma unroll
    for (int ni = 0; ni < 8; ++ni) {
        int gc = n0 + wn * 64 + ni * 8 + c2;
        float sw0 = as * wscale[gc],     bv0 = bias[gc];
        float sw1 = as * wscale[gc + 1], bv1 = bias[gc + 1];
#pragma unroll
        for (int mi = 0; mi < 2; ++mi) {
            int r = m0 + wm * 32 + mi * 16 + r4;
            float2 v0, v1;
            v0.x = fmaf(__int2float_rn(acc[mi][ni][0]), sw0, bv0);
            v0.y = fmaf(__int2float_rn(acc[mi][ni][1]), sw1, bv1);
            v1.x = fmaf(__int2float_rn(acc[mi][ni][2]), sw0, bv0);
            v1.y = fmaf(__int2float_rn(acc[mi][ni][3]), sw1, bv1);
            *reinterpret_cast<float2*>(&out[(size_t)r * ODIM + gc])       = v0;
            *reinterpret_cast<float2*>(&out[(size_t)(r + 8) * ODIM + gc]) = v1;
        }
    }
}

// ---------------------------------------------------------------------------
extern "C" void kernel_launch(void* const* d_in, const int* in_sizes, int n_in,
                              void* d_out, int out_size) {
    (void)in_sizes; (void)n_in; (void)out_size;
    const float* x         = (const float*)d_in[0];
    const float* weight    = (const float*)d_in[1];
    const float* bias      = (const float*)d_in[2];
    const float* act_scale = (const float*)d_in[3];
    const int*   act_zp    = (const int*)d_in[4];
    const float* wscale    = (const float*)d_in[5];
    const int*   wzp       = (const int*)d_in[6];
    float* out = (float*)d_out;

    cudaFuncSetAttribute(gemm_q_kernel, cudaFuncAttributeMaxDynamicSharedMemorySize, GEMM_SMEM);

    quant_fused_kernel<<<QB + QB2, 256>>>(x, act_scale, act_zp, weight, wscale, wzp);

    dim3 grid(ODIM / BN, NROWS / BM);   // (32, 32)
    gemm_q_kernel<<<grid, 256, GEMM_SMEM>>>(bias, act_scale, wscale, out);
}